// round 7
// baseline (speedup 1.0000x reference)
#include <cuda_runtime.h>
#include <cstdint>

#define NE 100000
#define NA 10000

// Scratch (static device globals — no allocation)
static __device__ float g_uncf[NA * 40 * 32];   // uncoupled features per atom (51 MB)
static __device__ float g_pool[NA * 40 * 32];   // pooled messages per atom (51 MB)
static __device__ int   g_count[NA];            // zero at start; re-zeroed by k_scan
static __device__ int   g_start[NA + 1];
static __device__ int   g_cursor[NA];
static __device__ int   g_eids[NE];             // CSR position -> edge id
static __device__ int   g_nbrs[NE];             // CSR position -> neighbor atom

__device__ __forceinline__ int dd2g(int dd) { return (dd == 0) ? 0 : (dd < 4) ? 1 : (dd < 13) ? 2 : 3; }
__device__ __forceinline__ int goff_u(int g) { return (g == 0) ? 0 : (g == 1) ? 1 : (g == 2) ? 13 : 94; }
__device__ __forceinline__ int goff_d(int g) { return (g == 0) ? 0 : (g == 1) ? 1 : (g == 2) ? 4 : 13; }
__device__ __forceinline__ int pow3g(int g)  { return (g == 0) ? 1 : (g == 1) ? 3 : (g == 2) ? 9 : 27; }

// ---------------------------------------------------------------------------
// CSR build
// ---------------------------------------------------------------------------
__global__ void k_hist(const int* __restrict__ centers) {
    int e = blockIdx.x * blockDim.x + threadIdx.x;
    if (e < NE) atomicAdd(&g_count[centers[e]], 1);
}

__global__ void __launch_bounds__(1024) k_scan() {
    __shared__ int warp_sums[32];
    const int t = threadIdx.x;
    const int base = t * 10;
    int local[10];
    int s = 0;
    #pragma unroll
    for (int i = 0; i < 10; i++) {
        int idx = base + i;
        int v = 0;
        if (idx < NA) { v = g_count[idx]; g_count[idx] = 0; }   // re-zero for next graph replay
        local[i] = s; s += v;
    }
    const int lane = t & 31, w = t >> 5;
    int pref = s;
    #pragma unroll
    for (int o = 1; o < 32; o <<= 1) {
        int x = __shfl_up_sync(0xffffffffu, pref, o);
        if (lane >= o) pref += x;
    }
    if (lane == 31) warp_sums[w] = pref;
    __syncthreads();
    if (w == 0) {
        int v = warp_sums[lane];
        #pragma unroll
        for (int o = 1; o < 32; o <<= 1) {
            int x = __shfl_up_sync(0xffffffffu, v, o);
            if (lane >= o) v += x;
        }
        warp_sums[lane] = v;
    }
    __syncthreads();
    int excl = pref - s + ((w > 0) ? warp_sums[w - 1] : 0);
    #pragma unroll
    for (int i = 0; i < 10; i++) {
        int idx = base + i;
        if (idx < NA) { g_start[idx] = excl + local[i]; g_cursor[idx] = excl + local[i]; }
    }
    if (t == 0) g_start[NA] = NE;
}

__global__ void k_scatter(const int* __restrict__ centers, const int* __restrict__ neighbors) {
    int e = blockIdx.x * blockDim.x + threadIdx.x;
    if (e < NE) {
        int pos = atomicAdd(&g_cursor[centers[e]], 1);
        g_eids[pos] = e;
        g_nbrs[pos] = neighbors[e];
    }
}

// ---------------------------------------------------------------------------
// compile-time-specialized uncoupled dot
// ---------------------------------------------------------------------------
template <int G>
__device__ __forceinline__ float uncf_dot(const float* __restrict__ Us,
                                          const float* __restrict__ fs,
                                          int ub, int lane)
{
    const int chb = 32 * (3 - G) + lane;
    float acc = Us[ub] * fs[chb];
    if (G >= 1) {
        #pragma unroll
        for (int mm = 0; mm < 3; mm++) acc = fmaf(Us[ub + 1 + mm], fs[128 + chb + mm * 96], acc);
    }
    if (G >= 2) {
        #pragma unroll
        for (int mm = 0; mm < 5; mm++) acc = fmaf(Us[ub + 4 + mm], fs[416 + chb + mm * 64], acc);
    }
    if (G >= 3) {
        #pragma unroll
        for (int mm = 0; mm < 7; mm++) acc = fmaf(Us[ub + 9 + mm], fs[736 + chb + mm * 32], acc);
    }
    return acc;
}

// ---------------------------------------------------------------------------
// K1: per-atom uncoupled features  g_uncf[n][dd][k]
// ---------------------------------------------------------------------------
__global__ void __launch_bounds__(256) k_uncf(
    const float* __restrict__ f0, const float* __restrict__ f1,
    const float* __restrict__ f2, const float* __restrict__ f3,
    const float* __restrict__ U0, const float* __restrict__ U1,
    const float* __restrict__ U2, const float* __restrict__ U3)
{
    __shared__ __align__(16) float fs[960];
    __shared__ float Us[526];
    const int n = blockIdx.x, t = threadIdx.x;
    if (t < 240) {
        float4 v;
        if      (t < 32)  v = ((const float4*)f0)[(size_t)n * 32 + t];
        else if (t < 104) v = ((const float4*)f1)[(size_t)n * 72 + (t - 32)];
        else if (t < 184) v = ((const float4*)f2)[(size_t)n * 80 + (t - 104)];
        else              v = ((const float4*)f3)[(size_t)n * 56 + (t - 184)];
        ((float4*)fs)[t] = v;
    }
    if (t == 0) Us[0] = U0[0];
    for (int i = t; i < 12;  i += 256) Us[1  + i] = U1[i];
    for (int i = t; i < 81;  i += 256) Us[13 + i] = U2[i];
    for (int i = t; i < 432; i += 256) Us[94 + i] = U3[i];
    __syncthreads();

    const int lane = t & 31, row = t >> 5;
    float* outp = g_uncf + (size_t)n * 1280;
    #pragma unroll
    for (int i = 0; i < 5; i++) {
        int dd = row + 8 * i;
        int g  = dd2g(dd);
        int d  = dd - goff_d(g);
        int ub = goff_u(g) + d * (g + 1) * (g + 1);
        float v;
        switch (g) {
            case 0:  v = uncf_dot<0>(Us, fs, ub, lane); break;
            case 1:  v = uncf_dot<1>(Us, fs, ub, lane); break;
            case 2:  v = uncf_dot<2>(Us, fs, ub, lane); break;
            default: v = uncf_dot<3>(Us, fs, ub, lane); break;
        }
        outp[dd * 32 + lane] = v;
    }
}

// ---------------------------------------------------------------------------
// K2: block per atom. Chunk ≤16 edges: cooperative R/S tables in smem,
//     then pure LDS/LDG/FMA message loop with register accumulators.
//     No atomics, no pool memset, no global materialization.
// ---------------------------------------------------------------------------
__global__ void __launch_bounds__(256) k_poolfused(
    const float* __restrict__ rr,
    const float* __restrict__ sh0, const float* __restrict__ sh1,
    const float* __restrict__ sh2, const float* __restrict__ sh3,
    const float* __restrict__ W0, const float* __restrict__ W1,
    const float* __restrict__ W2, const float* __restrict__ W3,
    const float* __restrict__ U0, const float* __restrict__ U1,
    const float* __restrict__ U2, const float* __restrict__ U3)
{
    __shared__ __align__(16) float Ws[2560];   // Wrad0..3 concat (offsets 0,1024,1792,2304)
    __shared__ __align__(16) float Rs[16 * 320]; // per-edge radial slices [e][c][lane]
    __shared__ __align__(16) float Ss[16 * 160]; // per-edge S table [e][dd*4+lp] (lp>g zero)
    __shared__ float Us[526];                   // U0..3 concat
    __shared__ float rbs[16][8];                // per-edge radial basis
    __shared__ float shv[16][16];               // per-edge sh values
    __shared__ int   eid_s[16];
    __shared__ int   nbr_s[16];

    const int t = threadIdx.x;
    for (int i = t; i < 1024; i += 256) Ws[i]        = W0[i];
    for (int i = t; i < 768;  i += 256) Ws[1024 + i] = W1[i];
    for (int i = t; i < 512;  i += 256) Ws[1792 + i] = W2[i];
    for (int i = t; i < 256;  i += 256) Ws[2304 + i] = W3[i];
    if (t == 0) Us[0] = U0[0];
    for (int i = t; i < 12;  i += 256) Us[1  + i] = U1[i];
    for (int i = t; i < 81;  i += 256) Us[13 + i] = U2[i];
    for (int i = t; i < 432; i += 256) Us[94 + i] = U3[i];
    __syncthreads();

    const int n = blockIdx.x;
    const int e0 = g_start[n], e1 = g_start[n + 1];
    const int lane = t & 31, row = t >> 5;

    // per-thread dd metadata (runtime row but fixed for whole kernel)
    int cb32_[5], dd32_[5], dd_[5];
    #pragma unroll
    for (int i = 0; i < 5; i++) {
        int dd = row + 8 * i;
        int g = dd2g(dd);
        cb32_[i] = (g * (g + 1) / 2) * 32;
        dd32_[i] = dd * 32;
        dd_[i]   = dd;
    }

    float acc[5] = {0.f, 0.f, 0.f, 0.f, 0.f};

    for (int c0 = e0; c0 < e1; c0 += 16) {
        const int cnt = min(16, e1 - c0);

        // stage edge ids / neighbors / radial basis (16 threads)
        if (t < cnt) {
            int e = g_eids[c0 + t];
            eid_s[t] = e;
            nbr_s[t] = g_nbrs[c0 + t];
            float rv = __ldg(rr + e);
            float s, c;
            __sincosf(rv * 0.62831853071795864769f, &s, &c);
            float scale = 0.5f * (c + 1.f) / (rv + 1e-6f);
            float sp = 0.f, sc = s;
            rbs[t][0] = sc * scale;
            #pragma unroll
            for (int i = 1; i < 8; i++) { float sn = 2.f * c * sc - sp; sp = sc; sc = sn; rbs[t][i] = sc * scale; }
        }
        __syncthreads();

        // stage sh: 16 values per edge
        {
            int el = t >> 4, sl = t & 15;
            if (el < cnt) {
                int e = eid_s[el];
                float v;
                if      (sl == 0) v = __ldg(sh0 + e);
                else if (sl < 4)  v = __ldg(sh1 + e * 3 + (sl - 1));
                else if (sl < 9)  v = __ldg(sh2 + e * 5 + (sl - 4));
                else              v = __ldg(sh3 + e * 7 + (sl - 9));
                shv[el][sl] = v;
            }
        }
        __syncthreads();

        // cooperative R tables: cnt*320 values
        {
            const int nR = cnt * 320;
            #pragma unroll
            for (int j = 0; j < 20; j++) {
                int v = t + 256 * j;
                if (v < nR) {
                    int e = v / 320;
                    int rem = v - e * 320;
                    int c = rem >> 5, ln = rem & 31;
                    int g = (c == 0) ? 0 : (c < 3) ? 1 : (c < 6) ? 2 : 3;
                    int lp = c - g * (g + 1) / 2;
                    int wo = (lp == 0) ? 0 : (lp == 1) ? 1024 : (lp == 2) ? 1792 : 2304;
                    int KL = 32 * (4 - lp);
                    int ch = 32 * (3 - g) + ln;
                    float a = 0.f;
                    #pragma unroll
                    for (int i = 0; i < 8; i++)
                        a = fmaf(rbs[e][i], Ws[wo + i * KL + ch], a);
                    Rs[v] = a;
                }
            }
        }
        // cooperative S tables: cnt*160 slots (lp>g slots written as 0)
        {
            const int nS = cnt * 160;
            #pragma unroll
            for (int j = 0; j < 10; j++) {
                int s = t + 256 * j;
                if (s < nS) {
                    int e = s / 160;
                    int rem = s - e * 160;
                    int dd = rem >> 2, lp = rem & 3;
                    int g = dd2g(dd);
                    float v = 0.f;
                    if (lp <= g) {
                        int d = dd - goff_d(g);
                        int ub = goff_u(g) + d * (g + 1) * (g + 1) + lp * lp;
                        for (int mm = 0; mm < 2 * lp + 1; mm++)
                            v = fmaf(Us[ub + mm], shv[e][lp * lp + mm], v);
                    }
                    Ss[s] = v;
                }
            }
        }
        __syncthreads();

        // message accumulation: pure LDS + coalesced L2 gather + FMA
        #pragma unroll 2
        for (int e = 0; e < cnt; e++) {
            const int rbase = e * 320 + lane;
            const float* uf = g_uncf + (size_t)nbr_s[e] * 1280 + lane;
            const float4* Sp = (const float4*)(Ss + e * 160);
            #pragma unroll
            for (int i = 0; i < 5; i++) {
                float4 s4 = Sp[dd_[i]];                // broadcast LDS.128 (Ss 16B-aligned)
                const float* Rp = Rs + rbase + cb32_[i];
                float unc = Rp[0] * s4.x;              // zero-padded S makes this unconditional
                unc = fmaf(Rp[32], s4.y, unc);
                unc = fmaf(Rp[64], s4.z, unc);
                unc = fmaf(Rp[96], s4.w, unc);
                acc[i] = fmaf(unc, __ldg(uf + dd32_[i]), acc[i]);
            }
        }
        __syncthreads();
    }

    float* pl = g_pool + (size_t)n * 1280 + lane;
    #pragma unroll
    for (int i = 0; i < 5; i++)
        pl[dd32_[i]] = acc[i];
}

// ---------------------------------------------------------------------------
// K3: 16 atoms per block, Wlin in smem, 4 atoms batched per weight load
// ---------------------------------------------------------------------------
__global__ void __launch_bounds__(256) k_out(
    const float* __restrict__ f0, const float* __restrict__ f1,
    const float* __restrict__ f2, const float* __restrict__ f3,
    const float* __restrict__ U0, const float* __restrict__ U1,
    const float* __restrict__ U2, const float* __restrict__ U3,
    const float* __restrict__ Wl0, const float* __restrict__ Wl1,
    const float* __restrict__ Wl2, const float* __restrict__ Wl3,
    float* __restrict__ out)
{
    extern __shared__ __align__(16) float Wsh[];   // 30720 floats
    __shared__ __align__(16) float ps[4][1280];
    __shared__ float xs[4][960];
    __shared__ float Us[526];
    const int t = threadIdx.x;

    for (int i = t; i < 7680; i += 256) {
        float4 v;
        if      (i < 4096) v = ((const float4*)Wl0)[i];
        else if (i < 6400) v = ((const float4*)Wl1)[i - 4096];
        else if (i < 7424) v = ((const float4*)Wl2)[i - 6400];
        else               v = ((const float4*)Wl3)[i - 7424];
        ((float4*)Wsh)[i] = v;
    }
    if (t == 0) Us[0] = U0[0];
    for (int i = t; i < 12;  i += 256) Us[1  + i] = U1[i];
    for (int i = t; i < 81;  i += 256) Us[13 + i] = U2[i];
    for (int i = t; i < 432; i += 256) Us[94 + i] = U3[i];
    __syncthreads();

    const int lane = t & 31, row = t >> 5;

    for (int b = 0; b < 4; b++) {
        const int nbase = blockIdx.x * 16 + b * 4;
        for (int i = t; i < 1280; i += 256) {
            int a = i / 320, j = i - a * 320;
            ((float4*)&ps[a][0])[j] = ((const float4*)(g_pool + (size_t)(nbase + a) * 1280))[j];
        }
        __syncthreads();

        #pragma unroll
        for (int i = 0; i < 4; i++) {
            int gm = row + 8 * i;
            if (gm < 30) {
                int g = (gm == 0) ? 0 : (gm < 5) ? 1 : (gm < 14) ? 2 : 3;
                int m = gm - ((g == 0) ? 0 : (g == 1) ? 1 : (g == 2) ? 5 : 14);
                int doff = goff_d(g);
                int gp1s = (g + 1) * (g + 1);
                int p3 = pow3g(g);
                int uo = goff_u(g) + m;
                float a0 = 0.f, a1 = 0.f, a2 = 0.f, a3 = 0.f;
                for (int d = 0; d < p3; d++) {
                    float u = Us[uo + d * gp1s];
                    int po = (doff + d) * 32 + lane;
                    a0 = fmaf(u, ps[0][po], a0);
                    a1 = fmaf(u, ps[1][po], a1);
                    a2 = fmaf(u, ps[2][po], a2);
                    a3 = fmaf(u, ps[3][po], a3);
                }
                xs[0][gm * 32 + lane] = a0;
                xs[1][gm * 32 + lane] = a1;
                xs[2][gm * 32 + lane] = a2;
                xs[3][gm * 32 + lane] = a3;
            }
        }
        __syncthreads();

        if (t < 240) {
            int l, m, q4, K, woff4; const float* F; size_t obase;
            if (t < 32)       { l = 0; K = 128; woff4 = 0;    F = f0; m = 0;            q4 = t;            obase = 0; }
            else if (t < 104) { l = 1; K = 96;  woff4 = 4096; F = f1; int u = t - 32;  m = u / 24; q4 = u % 24; obase = 1280000; }
            else if (t < 184) { l = 2; K = 64;  woff4 = 6400; F = f2; int u = t - 104; m = u / 16; q4 = u % 16; obase = 4160000; }
            else              { l = 3; K = 32;  woff4 = 7424; F = f3; int u = t - 184; m = u / 8;  q4 = u % 8;  obase = 7360000; }
            const int rows = 2 * l + 1;
            const int Kq = K >> 2;
            const int mrow = l * l + m;
            float4 a4[4];
            #pragma unroll
            for (int a = 0; a < 4; a++) a4[a] = make_float4(0.f, 0.f, 0.f, 0.f);
            for (int j = 0; j < 4 - l; j++) {
                int g = l + j;
                int gm = ((g == 0) ? 0 : (g == 1) ? 1 : (g == 2) ? 5 : 14) + mrow;
                const float4* Wr = (const float4*)Wsh + woff4 + (size_t)(32 * j) * Kq + q4;
                #pragma unroll
                for (int k = 0; k < 32; k++) {
                    float4 wv = Wr[(size_t)k * Kq];
                    #pragma unroll
                    for (int a = 0; a < 4; a++) {
                        float xv = xs[a][gm * 32 + k];
                        a4[a].x = fmaf(xv, wv.x, a4[a].x);
                        a4[a].y = fmaf(xv, wv.y, a4[a].y);
                        a4[a].z = fmaf(xv, wv.z, a4[a].z);
                        a4[a].w = fmaf(xv, wv.w, a4[a].w);
                    }
                }
            }
            #pragma unroll
            for (int a = 0; a < 4; a++) {
                size_t rel4 = ((size_t)(nbase + a) * rows + m) * Kq + q4;
                float4 fv = __ldg((const float4*)F + rel4);
                float4 ov = make_float4(fv.x + a4[a].x, fv.y + a4[a].y,
                                        fv.z + a4[a].z, fv.w + a4[a].w);
                ((float4*)out)[obase / 4 + rel4] = ov;
            }
        }
        __syncthreads();
    }
}

// ---------------------------------------------------------------------------
extern "C" void kernel_launch(void* const* d_in, const int* in_sizes, int n_in,
                              void* d_out, int out_size)
{
    (void)n_in; (void)out_size;
    const float *Rr, *SH[4], *FT[4], *WR[4], *UU[4], *WL[4];
    const int *CT, *NB;
    if (in_sizes[2] == 1280000) {
        Rr = (const float*)d_in[0];
        for (int l = 0; l < 4; l++) {
            SH[l] = (const float*)d_in[1 + 5 * l];
            FT[l] = (const float*)d_in[2 + 5 * l];
            WR[l] = (const float*)d_in[3 + 5 * l];
            UU[l] = (const float*)d_in[4 + 5 * l];
            WL[l] = (const float*)d_in[5 + 5 * l];
        }
        CT = (const int*)d_in[21]; NB = (const int*)d_in[22];
    } else {
        Rr = (const float*)d_in[0];
        for (int l = 0; l < 4; l++) {
            SH[l] = (const float*)d_in[1 + l];
            FT[l] = (const float*)d_in[5 + l];
            WR[l] = (const float*)d_in[9 + l];
            UU[l] = (const float*)d_in[13 + l];
            WL[l] = (const float*)d_in[17 + l];
        }
        CT = (const int*)d_in[21]; NB = (const int*)d_in[22];
    }

    cudaFuncSetAttribute(k_out, cudaFuncAttributeMaxDynamicSharedMemorySize, 30720 * 4);

    // g_count is zero at first call (static init) and re-zeroed inside k_scan.
    k_hist<<<(NE + 255) / 256, 256>>>(CT);
    k_scan<<<1, 1024>>>();
    k_scatter<<<(NE + 255) / 256, 256>>>(CT, NB);
    k_uncf<<<NA, 256>>>(FT[0], FT[1], FT[2], FT[3], UU[0], UU[1], UU[2], UU[3]);
    k_poolfused<<<NA, 256>>>(Rr, SH[0], SH[1], SH[2], SH[3],
                             WR[0], WR[1], WR[2], WR[3],
                             UU[0], UU[1], UU[2], UU[3]);
    k_out<<<NA / 16, 256, 30720 * 4>>>(FT[0], FT[1], FT[2], FT[3],
                                       UU[0], UU[1], UU[2], UU[3],
                                       WL[0], WL[1], WL[2], WL[3], (float*)d_out);
}

// round 8
// speedup vs baseline: 1.9744x; 1.9744x over previous
#include <cuda_runtime.h>
#include <cstdint>

#define NE 100000
#define NA 10000

// Scratch (static device globals — no allocation)
static __device__ float g_uncf[NA * 40 * 32];   // uncoupled features per atom
static __device__ float g_pool[NA * 40 * 32];   // pooled messages per atom

__device__ __forceinline__ int dd2g(int dd) { return (dd == 0) ? 0 : (dd < 4) ? 1 : (dd < 13) ? 2 : 3; }
__device__ __forceinline__ int goff_u(int g) { return (g == 0) ? 0 : (g == 1) ? 1 : (g == 2) ? 13 : 94; }
__device__ __forceinline__ int goff_d(int g) { return (g == 0) ? 0 : (g == 1) ? 1 : (g == 2) ? 4 : 13; }
__device__ __forceinline__ int pow3g(int g)  { return (g == 0) ? 1 : (g == 1) ? 3 : (g == 2) ? 9 : 27; }

// ---------------------------------------------------------------------------
// compile-time-specialized uncoupled dot
// ---------------------------------------------------------------------------
template <int G>
__device__ __forceinline__ float uncf_dot(const float* __restrict__ Us,
                                          const float* __restrict__ fs,
                                          int ub, int lane)
{
    const int chb = 32 * (3 - G) + lane;
    float acc = Us[ub] * fs[chb];
    if (G >= 1) {
        #pragma unroll
        for (int mm = 0; mm < 3; mm++) acc = fmaf(Us[ub + 1 + mm], fs[128 + chb + mm * 96], acc);
    }
    if (G >= 2) {
        #pragma unroll
        for (int mm = 0; mm < 5; mm++) acc = fmaf(Us[ub + 4 + mm], fs[416 + chb + mm * 64], acc);
    }
    if (G >= 3) {
        #pragma unroll
        for (int mm = 0; mm < 7; mm++) acc = fmaf(Us[ub + 9 + mm], fs[736 + chb + mm * 32], acc);
    }
    return acc;
}

// ---------------------------------------------------------------------------
// K1: per-atom uncoupled features  g_uncf[n][dd][k]   (measured 31 us)
// ---------------------------------------------------------------------------
__global__ void __launch_bounds__(256) k_uncf(
    const float* __restrict__ f0, const float* __restrict__ f1,
    const float* __restrict__ f2, const float* __restrict__ f3,
    const float* __restrict__ U0, const float* __restrict__ U1,
    const float* __restrict__ U2, const float* __restrict__ U3)
{
    __shared__ __align__(16) float fs[960];
    __shared__ float Us[526];
    const int n = blockIdx.x, t = threadIdx.x;
    if (t < 240) {
        float4 v;
        if      (t < 32)  v = ((const float4*)f0)[(size_t)n * 32 + t];
        else if (t < 104) v = ((const float4*)f1)[(size_t)n * 72 + (t - 32)];
        else if (t < 184) v = ((const float4*)f2)[(size_t)n * 80 + (t - 104)];
        else              v = ((const float4*)f3)[(size_t)n * 56 + (t - 184)];
        ((float4*)fs)[t] = v;
    }
    if (t == 0) Us[0] = U0[0];
    for (int i = t; i < 12;  i += 256) Us[1  + i] = U1[i];
    for (int i = t; i < 81;  i += 256) Us[13 + i] = U2[i];
    for (int i = t; i < 432; i += 256) Us[94 + i] = U3[i];
    __syncthreads();

    const int lane = t & 31, row = t >> 5;
    float* outp = g_uncf + (size_t)n * 1280;
    #pragma unroll
    for (int i = 0; i < 5; i++) {
        int dd = row + 8 * i;
        int g  = dd2g(dd);
        int d  = dd - goff_d(g);
        int ub = goff_u(g) + d * (g + 1) * (g + 1);
        float v;
        switch (g) {
            case 0:  v = uncf_dot<0>(Us, fs, ub, lane); break;
            case 1:  v = uncf_dot<1>(Us, fs, ub, lane); break;
            case 2:  v = uncf_dot<2>(Us, fs, ub, lane); break;
            default: v = uncf_dot<3>(Us, fs, ub, lane); break;
        }
        outp[dd * 32 + lane] = v;
    }
}

// ---------------------------------------------------------------------------
// K2: warp per edge (R2 version — best measured edge strategy).
//     Radial via sin recurrence, S table cooperatively in smem,
//     gather unc_f[neighbor], multiply, atomicAdd into g_pool[center].
// ---------------------------------------------------------------------------
__global__ void __launch_bounds__(256) k_edge(
    const float* __restrict__ rr,
    const float* __restrict__ sh0, const float* __restrict__ sh1,
    const float* __restrict__ sh2, const float* __restrict__ sh3,
    const float* __restrict__ W0, const float* __restrict__ W1,
    const float* __restrict__ W2, const float* __restrict__ W3,
    const float* __restrict__ U0, const float* __restrict__ U1,
    const float* __restrict__ U2, const float* __restrict__ U3,
    const int* __restrict__ centers, const int* __restrict__ neighbors)
{
    __shared__ float Ws[2560];          // Wrad0..3 concat (offsets 0,1024,1792,2304)
    __shared__ float Us[526];           // U0..3 concat
    __shared__ float4 seS[8][40];       // per-warp S table (float4 → 16B aligned)
    __shared__ float  shS[8][16];       // per-warp sh values

    const int t = threadIdx.x;
    for (int i = t; i < 1024; i += 256) Ws[i]        = W0[i];
    for (int i = t; i < 768;  i += 256) Ws[1024 + i] = W1[i];
    for (int i = t; i < 512;  i += 256) Ws[1792 + i] = W2[i];
    for (int i = t; i < 256;  i += 256) Ws[2304 + i] = W3[i];
    if (t == 0) Us[0] = U0[0];
    for (int i = t; i < 12;  i += 256) Us[1  + i] = U1[i];
    for (int i = t; i < 81;  i += 256) Us[13 + i] = U2[i];
    for (int i = t; i < 432; i += 256) Us[94 + i] = U3[i];
    __syncthreads();

    const int w = t >> 5, lane = t & 31;
    const int e = blockIdx.x * 8 + w;
    if (e >= NE) return;

    // radial basis via sin recurrence
    const float rv = __ldg(rr + e);
    float s, c;
    __sincosf(rv * 0.62831853071795864769f, &s, &c);
    const float scale = 0.5f * (c + 1.f) / (rv + 1e-6f);
    float rb[8];
    {
        float sp = 0.f, sc = s;
        rb[0] = sc * scale;
        #pragma unroll
        for (int i = 1; i < 8; i++) { float sn = 2.f * c * sc - sp; sp = sc; sc = sn; rb[i] = sc * scale; }
    }

    // radial values per lane: R[cmb], cmb = g*(g+1)/2 + lp, at channel 32*(3-g)+lane
    float R[10];
    #pragma unroll
    for (int g = 0; g < 4; g++) {
        const int ch = 32 * (3 - g) + lane;
        #pragma unroll
        for (int lp = 0; lp <= g; lp++) {
            const int wo = (lp == 0) ? 0 : (lp == 1) ? 1024 : (lp == 2) ? 1792 : 2304;
            const int KL = 32 * (4 - lp);
            float acc = 0.f;
            #pragma unroll
            for (int i = 0; i < 8; i++)
                acc = fmaf(rb[i], Ws[wo + i * KL + ch], acc);
            R[g * (g + 1) / 2 + lp] = acc;
        }
    }

    // sh values to smem (16 per edge)
    if (lane < 16) {
        float v;
        if      (lane == 0) v = __ldg(sh0 + e);
        else if (lane < 4)  v = __ldg(sh1 + e * 3 + (lane - 1));
        else if (lane < 9)  v = __ldg(sh2 + e * 5 + (lane - 4));
        else                v = __ldg(sh3 + e * 7 + (lane - 9));
        shS[w][lane] = v;
    }
    __syncwarp();

    // Phase A: cooperative S table.  S[dd][lp] = sum_mm U_g[d][lp^2+mm]*sh_lp[mm]
    {
        float* se = (float*)&seS[w][0];
        #pragma unroll
        for (int i = 0; i < 5; i++) {
            int slot = lane + 32 * i;         // 160 slots = 40 dd x 4 lp
            int dd = slot >> 2, lp = slot & 3;
            int g = dd2g(dd);
            float v = 0.f;
            if (lp <= g) {
                int d = dd - goff_d(g);
                int ub = goff_u(g) + d * (g + 1) * (g + 1) + lp * lp;
                for (int mm = 0; mm < 2 * lp + 1; mm++)
                    v = fmaf(Us[ub + mm], shS[w][lp * lp + mm], v);
            }
            se[slot] = v;
        }
    }
    __syncwarp();

    // Phase B: message + scatter
    const int nbr = __ldg(neighbors + e);
    const int ctr = __ldg(centers + e);
    const float* uf = g_uncf + (size_t)nbr * 1280 + lane;
    float*       pl = g_pool + (size_t)ctr * 1280 + lane;
    #pragma unroll
    for (int dd = 0; dd < 40; dd++) {
        const int g = (dd == 0) ? 0 : (dd < 4) ? 1 : (dd < 13) ? 2 : 3;   // folded at unroll
        const int cb = g * (g + 1) / 2;
        float4 s4 = seS[w][dd];
        float unc = R[cb] * s4.x;
        if (g >= 1) unc = fmaf(R[cb + 1], s4.y, unc);
        if (g >= 2) unc = fmaf(R[cb + 2], s4.z, unc);
        if (g >= 3) unc = fmaf(R[cb + 3], s4.w, unc);
        float f = __ldg(uf + dd * 32);
        atomicAdd(pl + dd * 32, unc * f);
    }
}

// ---------------------------------------------------------------------------
// K3: 4 atoms per block; weights via LDG float4 (each read feeds 16 FMAs).
//     Cuts Wlin L2 traffic 4x vs R2's per-atom version, no big-smem cliff.
// ---------------------------------------------------------------------------
__global__ void __launch_bounds__(256) k_out4(
    const float* __restrict__ f0, const float* __restrict__ f1,
    const float* __restrict__ f2, const float* __restrict__ f3,
    const float* __restrict__ U0, const float* __restrict__ U1,
    const float* __restrict__ U2, const float* __restrict__ U3,
    const float* __restrict__ Wl0, const float* __restrict__ Wl1,
    const float* __restrict__ Wl2, const float* __restrict__ Wl3,
    float* __restrict__ out)
{
    __shared__ __align__(16) float ps[4][1280];
    __shared__ float xs[4][960];
    __shared__ float Us[526];
    const int t = threadIdx.x;
    const int nbase = blockIdx.x * 4;

    for (int i = t; i < 1280; i += 256) {
        int a = i / 320, j = i - a * 320;
        ((float4*)&ps[a][0])[j] = ((const float4*)(g_pool + (size_t)(nbase + a) * 1280))[j];
    }
    if (t == 0) Us[0] = U0[0];
    for (int i = t; i < 12;  i += 256) Us[1  + i] = U1[i];
    for (int i = t; i < 81;  i += 256) Us[13 + i] = U2[i];
    for (int i = t; i < 432; i += 256) Us[94 + i] = U3[i];
    __syncthreads();

    const int lane = t & 31, row = t >> 5;

    // couple for 4 atoms: x_g[m][k] = sum_d U_g[d][m] * pool[g][d][k]
    #pragma unroll
    for (int i = 0; i < 4; i++) {
        int gm = row + 8 * i;
        if (gm < 30) {
            int g = (gm == 0) ? 0 : (gm < 5) ? 1 : (gm < 14) ? 2 : 3;
            int m = gm - ((g == 0) ? 0 : (g == 1) ? 1 : (g == 2) ? 5 : 14);
            int doff = goff_d(g);
            int gp1s = (g + 1) * (g + 1);
            int p3 = pow3g(g);
            int uo = goff_u(g) + m;
            float a0 = 0.f, a1 = 0.f, a2 = 0.f, a3 = 0.f;
            for (int d = 0; d < p3; d++) {
                float u = Us[uo + d * gp1s];
                int po = (doff + d) * 32 + lane;
                a0 = fmaf(u, ps[0][po], a0);
                a1 = fmaf(u, ps[1][po], a1);
                a2 = fmaf(u, ps[2][po], a2);
                a3 = fmaf(u, ps[3][po], a3);
            }
            xs[0][gm * 32 + lane] = a0;
            xs[1][gm * 32 + lane] = a1;
            xs[2][gm * 32 + lane] = a2;
            xs[3][gm * 32 + lane] = a3;
        }
    }
    __syncthreads();

    if (t < 240) {
        int l, m, q4, K; const float* W; const float* F; size_t obase;
        if (t < 32)       { l = 0; K = 128; W = Wl0; F = f0; m = 0;            q4 = t;            obase = 0; }
        else if (t < 104) { l = 1; K = 96;  W = Wl1; F = f1; int u = t - 32;  m = u / 24; q4 = u % 24; obase = 1280000; }
        else if (t < 184) { l = 2; K = 64;  W = Wl2; F = f2; int u = t - 104; m = u / 16; q4 = u % 16; obase = 4160000; }
        else              { l = 3; K = 32;  W = Wl3; F = f3; int u = t - 184; m = u / 8;  q4 = u % 8;  obase = 7360000; }
        const int rows = 2 * l + 1;
        const int Kq = K >> 2;
        const int mrow = l * l + m;
        float4 a4[4];
        #pragma unroll
        for (int a = 0; a < 4; a++) a4[a] = make_float4(0.f, 0.f, 0.f, 0.f);
        for (int j = 0; j < 4 - l; j++) {
            int g = l + j;
            int gm = ((g == 0) ? 0 : (g == 1) ? 1 : (g == 2) ? 5 : 14) + mrow;
            const float4* Wr = (const float4*)W + (size_t)(32 * j) * Kq + q4;
            #pragma unroll
            for (int k = 0; k < 32; k++) {
                float4 wv = __ldg(Wr + (size_t)k * Kq);
                #pragma unroll
                for (int a = 0; a < 4; a++) {
                    float xv = xs[a][gm * 32 + k];
                    a4[a].x = fmaf(xv, wv.x, a4[a].x);
                    a4[a].y = fmaf(xv, wv.y, a4[a].y);
                    a4[a].z = fmaf(xv, wv.z, a4[a].z);
                    a4[a].w = fmaf(xv, wv.w, a4[a].w);
                }
            }
        }
        #pragma unroll
        for (int a = 0; a < 4; a++) {
            size_t rel4 = ((size_t)(nbase + a) * rows + m) * Kq + q4;
            float4 fv = __ldg((const float4*)F + rel4);
            float4 ov = make_float4(fv.x + a4[a].x, fv.y + a4[a].y,
                                    fv.z + a4[a].z, fv.w + a4[a].w);
            ((float4*)out)[obase / 4 + rel4] = ov;
        }
    }
}

// ---------------------------------------------------------------------------
extern "C" void kernel_launch(void* const* d_in, const int* in_sizes, int n_in,
                              void* d_out, int out_size)
{
    (void)n_in; (void)out_size;
    const float *Rr, *SH[4], *FT[4], *WR[4], *UU[4], *WL[4];
    const int *CT, *NB;
    if (in_sizes[2] == 1280000) {
        Rr = (const float*)d_in[0];
        for (int l = 0; l < 4; l++) {
            SH[l] = (const float*)d_in[1 + 5 * l];
            FT[l] = (const float*)d_in[2 + 5 * l];
            WR[l] = (const float*)d_in[3 + 5 * l];
            UU[l] = (const float*)d_in[4 + 5 * l];
            WL[l] = (const float*)d_in[5 + 5 * l];
        }
        CT = (const int*)d_in[21]; NB = (const int*)d_in[22];
    } else {
        Rr = (const float*)d_in[0];
        for (int l = 0; l < 4; l++) {
            SH[l] = (const float*)d_in[1 + l];
            FT[l] = (const float*)d_in[5 + l];
            WR[l] = (const float*)d_in[9 + l];
            UU[l] = (const float*)d_in[13 + l];
            WL[l] = (const float*)d_in[17 + l];
        }
        CT = (const int*)d_in[21]; NB = (const int*)d_in[22];
    }

    void* pptr = nullptr;
    cudaGetSymbolAddress(&pptr, g_pool);
    cudaMemsetAsync(pptr, 0, sizeof(float) * (size_t)NA * 1280, 0);

    k_uncf<<<NA, 256>>>(FT[0], FT[1], FT[2], FT[3], UU[0], UU[1], UU[2], UU[3]);
    k_edge<<<NE / 8, 256>>>(Rr, SH[0], SH[1], SH[2], SH[3],
                            WR[0], WR[1], WR[2], WR[3],
                            UU[0], UU[1], UU[2], UU[3], CT, NB);
    k_out4<<<NA / 4, 256>>>(FT[0], FT[1], FT[2], FT[3],
                            UU[0], UU[1], UU[2], UU[3],
                            WL[0], WL[1], WL[2], WL[3], (float*)d_out);
}